// round 10
// baseline (speedup 1.0000x reference)
#include <cuda_runtime.h>
#include <cstdint>

#define N_NODES 100000
#define N_EDGES 3200000
#define F_IN    512
#define HID     16
#define N_CLASSES 40
#define CAP     128   // per-node in-edge bucket capacity (deg~Poisson(32): P(>127)~0)

#define GW_WARPS 8    // warps per gemm block
#define GW_NPW   16   // nodes per warp
#define GB_GEMM  782  // ceil(100000 / (8*16))

// Scratch (device globals: allocation-free)
__device__ float g_hs[N_NODES * HID];      // hs = relu(x@W1^T+b1)@Wg^T * dinv
__device__ int   g_cnt[N_NODES];           // in-degree counter / slot allocator
__device__ int   g_slots[N_NODES * CAP];   // bucketed CSR: src ids per dst
__device__ int   g_is64;

// ---------- packed f32x2 helpers (Blackwell) ----------
__device__ __forceinline__ unsigned long long pack2(float x, float y) {
    unsigned long long r;
    asm("mov.b64 %0, {%1,%2};" : "=l"(r) : "f"(x), "f"(y));
    return r;
}
__device__ __forceinline__ void unpack2(unsigned long long v, float& x, float& y) {
    asm("mov.b64 {%0,%1}, %2;" : "=f"(x), "=f"(y) : "l"(v));
}
__device__ __forceinline__ void fma2(unsigned long long& a, unsigned long long b, unsigned long long c) {
    asm("fma.rn.f32x2 %0, %1, %2, %0;" : "+l"(a) : "l"(b), "l"(c));
}
__device__ __forceinline__ unsigned long long add2(unsigned long long a, unsigned long long b) {
    unsigned long long r;
    asm("add.rn.f32x2 %0, %1, %2;" : "=l"(r) : "l"(a), "l"(b));
    return r;
}
__device__ __forceinline__ unsigned long long shfl_xor64(unsigned long long v, int off) {
    unsigned lo = (unsigned)v, hi = (unsigned)(v >> 32);
    lo = __shfl_xor_sync(0xFFFFFFFFu, lo, off);
    hi = __shfl_xor_sync(0xFFFFFFFFu, hi, off);
    return ((unsigned long long)hi << 32) | lo;
}

// ---------- dummy: shifts launch index so ncu (-s5 -c1, 4th launch) lands on gemm1 ----------
__global__ void k_dummy() {}

// ---------- prep: zero counters + dtype detect (int64 vs int32 edge_index) ----------
__global__ __launch_bounds__(256) void k_prep(const void* e) {
    int i = blockIdx.x * 256 + threadIdx.x;
    if (i < N_NODES) g_cnt[i] = 0;
    if (blockIdx.x == 0 && threadIdx.x < 64) {
        int t = threadIdx.x;
        const long long* p = (const long long*)e;
        long long v = p[(long long)t * (N_EDGES / 64)];   // max 25.2MB, always in-bounds
        int ok = (v >= 0 && v < N_NODES) ? 1 : 0;
        unsigned m = __ballot_sync(0xFFFFFFFFu, ok);
        __shared__ unsigned sm[2];
        if ((t & 31) == 0) sm[t >> 5] = m;
        __syncthreads();
        if (t == 0) g_is64 = (sm[0] == 0xFFFFFFFFu && sm[1] == 0xFFFFFFFFu) ? 1 : 0;
    }
}

// ---------- fill bucketed CSR: 4 edges/thread, batched atomics then stores ----------
__global__ __launch_bounds__(256) void k_fill(const void* __restrict__ e) {
    int t = blockIdx.x * 256 + threadIdx.x;
    if (t >= N_EDGES / 4) return;
    int s[4], d[4];
    if (g_is64) {
        const longlong4* ps = (const longlong4*)e;
        const longlong4* pd = (const longlong4*)((const long long*)e + N_EDGES);
        longlong4 a = ps[t];
        longlong4 b = pd[t];
        s[0] = (int)a.x; s[1] = (int)a.y; s[2] = (int)a.z; s[3] = (int)a.w;
        d[0] = (int)b.x; d[1] = (int)b.y; d[2] = (int)b.z; d[3] = (int)b.w;
    } else {
        const int4* ps = (const int4*)e;
        const int4* pd = (const int4*)((const int*)e + N_EDGES);
        int4 a = ps[t];
        int4 b = pd[t];
        s[0] = a.x; s[1] = a.y; s[2] = a.z; s[3] = a.w;
        d[0] = b.x; d[1] = b.y; d[2] = b.z; d[3] = b.w;
    }
    int pos[4];
    #pragma unroll
    for (int k = 0; k < 4; k++) pos[k] = atomicAdd(&g_cnt[d[k]], 1);
    #pragma unroll
    for (int k = 0; k < 4; k++)
        if (pos[k] < CAP) g_slots[d[k] * CAP + pos[k]] = s[k];
}

// ---------- K0 (warp-per-node, coalesced): hs = relu(x@W1^T+b1)@Wg^T * rsqrt(deg) ----------
// Lane L of pass i reads float4 #(i*32+L) of the node's row -> warp LDG.128 spans
// 512B contiguous (nL=4, no L1tex wavefront blowup). Lane's fixed k-slice hits
// wX[i][d][c][lane] (16B lane stride, conflict-free). Staged shfl reduction, smem
// h1 exchange, epilogue fuses bias+relu+Wg+dinv.
__global__ __launch_bounds__(256) void k_gemm1(
    const float4* __restrict__ x4,
    const float* __restrict__ W1,
    const float* __restrict__ b1,
    const float* __restrict__ Wg)
{
    __shared__ ulonglong2 wX[4][4][4][32];                 // 32KB
    __shared__ float sWgT[HID * HID];                      // transposed: [j][j2]
    __shared__ float sb1[HID];
    __shared__ unsigned long long sh1[GW_WARPS][8];

    int tid = threadIdx.x;
    // weight staging: idx -> (i,d,c,L); k = 4*(i*32+L)+d; j0 = 4c
    for (int idx = tid; idx < 2048; idx += 256) {
        int i = idx >> 9, rem = idx & 511;
        int d = rem >> 7, rem2 = rem & 127;
        int c = rem2 >> 5, L = rem2 & 31;
        int k = 4 * (i * 32 + L) + d;
        int j0 = 4 * c;
        ulonglong2 v;
        v.x = pack2(W1[(j0 + 0) * F_IN + k], W1[(j0 + 1) * F_IN + k]);
        v.y = pack2(W1[(j0 + 2) * F_IN + k], W1[(j0 + 3) * F_IN + k]);
        wX[i][d][c][L] = v;
    }
    for (int idx = tid; idx < HID * HID; idx += 256)
        sWgT[idx] = Wg[(idx & 15) * HID + (idx >> 4)];     // sWgT[j*16+j2] = Wg[j2][j]
    for (int idx = tid; idx < HID; idx += 256) sb1[idx] = b1[idx];
    __syncthreads();

    int wid = tid >> 5, lane = tid & 31;
    int w0 = (blockIdx.x * GW_WARPS + wid) * GW_NPW;

    float4 xv[4], xn[4];
    {
        int nc = w0 < N_NODES ? w0 : N_NODES - 1;
        #pragma unroll
        for (int i = 0; i < 4; i++)
            xv[i] = __ldg(x4 + (long long)nc * (F_IN / 4) + i * 32 + lane);
    }

    #pragma unroll 2
    for (int t = 0; t < GW_NPW; t++) {
        int node = w0 + t;
        if (t + 1 < GW_NPW) {
            int nn = node + 1 < N_NODES ? node + 1 : N_NODES - 1;
            #pragma unroll
            for (int i = 0; i < 4; i++)
                xn[i] = __ldg(x4 + (long long)nn * (F_IN / 4) + i * 32 + lane);
        }

        unsigned long long acc[8];
        #pragma unroll
        for (int m = 0; m < 8; m++) acc[m] = 0ull;

        #pragma unroll
        for (int i = 0; i < 4; i++) {
            float xs[4] = {xv[i].x, xv[i].y, xv[i].z, xv[i].w};
            #pragma unroll
            for (int d = 0; d < 4; d++) {
                unsigned long long xx = pack2(xs[d], xs[d]);
                ulonglong2 q0 = wX[i][d][0][lane];
                fma2(acc[0], xx, q0.x); fma2(acc[1], xx, q0.y);
                ulonglong2 q1 = wX[i][d][1][lane];
                fma2(acc[2], xx, q1.x); fma2(acc[3], xx, q1.y);
                ulonglong2 q2 = wX[i][d][2][lane];
                fma2(acc[4], xx, q2.x); fma2(acc[5], xx, q2.y);
                ulonglong2 q3 = wX[i][d][3][lane];
                fma2(acc[6], xx, q3.x); fma2(acc[7], xx, q3.y);
            }
        }
        #pragma unroll
        for (int i = 0; i < 4; i++) xv[i] = xn[i];

        // staged cross-lane reduction: bit16 (8->4), bit8 (4->2), bit4 (2->1), bits 2,1 full
        bool hi16 = (lane & 16) != 0;
        unsigned long long a4[4];
        #pragma unroll
        for (int m = 0; m < 4; m++) {
            unsigned long long send = hi16 ? acc[m] : acc[m + 4];
            unsigned long long own  = hi16 ? acc[m + 4] : acc[m];
            a4[m] = add2(own, shfl_xor64(send, 16));
        }
        bool hi8 = (lane & 8) != 0;
        unsigned long long a2[2];
        #pragma unroll
        for (int m = 0; m < 2; m++) {
            unsigned long long send = hi8 ? a2[0] * 0 + (hi8 ? a4[m] : a4[m + 2]) : a4[m + 2];
            unsigned long long own  = hi8 ? a4[m + 2] : a4[m];
            send = hi8 ? a4[m] : a4[m + 2];
            a2[m] = add2(own, shfl_xor64(send, 8));
        }
        bool hi4 = (lane & 4) != 0;
        unsigned long long a1;
        {
            unsigned long long send = hi4 ? a2[0] : a2[1];
            unsigned long long own  = hi4 ? a2[1] : a2[0];
            a1 = add2(own, shfl_xor64(send, 4));
        }
        a1 = add2(a1, shfl_xor64(a1, 2));
        a1 = add2(a1, shfl_xor64(a1, 1));
        int m_own = (lane >> 2) & 7;      // lane holds (h1[2m], h1[2m+1])

        __syncwarp();
        if ((lane & 3) == 0) sh1[wid][m_own] = a1;
        __syncwarp();

        float hv[HID];
        #pragma unroll
        for (int p = 0; p < 8; p++) {
            float lo, hh;
            unpack2(sh1[wid][p], lo, hh);
            float va = lo + sb1[2 * p];
            float vb = hh + sb1[2 * p + 1];
            hv[2 * p]     = va > 0.f ? va : 0.f;
            hv[2 * p + 1] = vb > 0.f ? vb : 0.f;
        }

        if (node < N_NODES) {
            int j2 = lane & 15;
            float s = 0.f;
            #pragma unroll
            for (int j = 0; j < HID; j++) s += hv[j] * sWgT[j * HID + j2];
            float dvv = rsqrtf((float)(__ldg(&g_cnt[node]) + 1));
            if (lane < 16) g_hs[(long long)node * HID + j2] = s * dvv;
        }
    }
}

// ---------- fused gather + final ----------
__global__ __launch_bounds__(256) void k_gather_final(
    const float* __restrict__ W2,
    const float* __restrict__ b2,
    const float* __restrict__ bg,
    float* __restrict__ out)
{
    __shared__ float sW2[N_CLASSES * HID];
    __shared__ float sb2[N_CLASSES];
    __shared__ float sbg[HID];
    int tid = threadIdx.x;
    for (int i = tid; i < N_CLASSES * HID; i += 256) sW2[i] = W2[i];
    if (tid < N_CLASSES) sb2[tid] = b2[tid];
    if (tid < HID) sbg[tid] = bg[tid];
    __syncthreads();

    int warp = (blockIdx.x * 256 + tid) >> 5;
    if (warp >= N_NODES) return;
    int lane = tid & 31;
    int g = lane >> 2;        // edge group 0..7
    int f = lane & 3;         // float4 index 0..3

    int cnt = __ldg(&g_cnt[warp]);
    int m = cnt < CAP ? cnt : CAP;
    const int* slots = g_slots + warp * CAP;

    int s0 = 0, s1 = 0;
    if (lane < m)      s0 = __ldg(slots + lane);
    if (32 + lane < m) s1 = __ldg(slots + 32 + lane);

    float ax = 0.f, ay = 0.f, az = 0.f, aw = 0.f;
    int lim = m < 64 ? m : 64;
    #pragma unroll 4
    for (int e = 0; e < lim; e += 8) {
        int idx = e + g;
        int sv = (e < 32) ? __shfl_sync(0xFFFFFFFFu, s0, idx)
                          : __shfl_sync(0xFFFFFFFFu, s1, idx - 32);
        if (idx < lim) {
            float4 v = __ldg((const float4*)(g_hs + (long long)sv * HID) + f);
            ax += v.x; ay += v.y; az += v.z; aw += v.w;
        }
    }
    for (int e = 64; e < m; e += 8) {   // rare tail (deg > 64)
        int idx = e + g;
        if (idx < m) {
            int sv = __ldg(slots + idx);
            float4 v = __ldg((const float4*)(g_hs + (long long)sv * HID) + f);
            ax += v.x; ay += v.y; az += v.z; aw += v.w;
        }
    }
    #pragma unroll
    for (int off = 4; off < 32; off <<= 1) {
        ax += __shfl_xor_sync(0xFFFFFFFFu, ax, off);
        ay += __shfl_xor_sync(0xFFFFFFFFu, ay, off);
        az += __shfl_xor_sync(0xFFFFFFFFu, az, off);
        aw += __shfl_xor_sync(0xFFFFFFFFu, aw, off);
    }

    float4 self = __ldg((const float4*)(g_hs + (long long)warp * HID) + f);
    float dv = rsqrtf((float)(cnt + 1));
    float hp[4];
    {
        float t0 = (ax + self.x) * dv + sbg[4 * f + 0];
        float t1 = (ay + self.y) * dv + sbg[4 * f + 1];
        float t2 = (az + self.z) * dv + sbg[4 * f + 2];
        float t3 = (aw + self.w) * dv + sbg[4 * f + 3];
        hp[0] = t0 > 0.f ? t0 : 0.f;
        hp[1] = t1 > 0.f ? t1 : 0.f;
        hp[2] = t2 > 0.f ? t2 : 0.f;
        hp[3] = t3 > 0.f ? t3 : 0.f;
    }

    float h[HID];
    #pragma unroll
    for (int a = 0; a < 4; a++) {
        #pragma unroll
        for (int b = 0; b < 4; b++)
            h[a * 4 + b] = __shfl_sync(0xFFFFFFFFu, hp[b], a);
    }

    float l1 = sb2[lane];
    #pragma unroll
    for (int j = 0; j < HID; j++) l1 += h[j] * sW2[lane * HID + j];
    float l2 = -3.4e38f;
    if (lane < N_CLASSES - 32) {
        l2 = sb2[32 + lane];
        #pragma unroll
        for (int j = 0; j < HID; j++) l2 += h[j] * sW2[(32 + lane) * HID + j];
    }

    float mx = fmaxf(l1, l2);
    #pragma unroll
    for (int off = 16; off >= 1; off >>= 1)
        mx = fmaxf(mx, __shfl_xor_sync(0xFFFFFFFFu, mx, off));
    float ee = __expf(l1 - mx) + (lane < N_CLASSES - 32 ? __expf(l2 - mx) : 0.f);
    #pragma unroll
    for (int off = 16; off >= 1; off >>= 1)
        ee += __shfl_xor_sync(0xFFFFFFFFu, ee, off);
    float lse = __logf(ee) + mx;

    float* o = out + (long long)warp * N_CLASSES;
    o[lane] = l1 - lse;
    if (lane < N_CLASSES - 32) o[32 + lane] = l2 - lse;
}

extern "C" void kernel_launch(void* const* d_in, const int* in_sizes, int n_in,
                              void* d_out, int out_size) {
    const float* x  = (const float*)d_in[0];
    const void*  e  = d_in[1];
    const float* W1 = (const float*)d_in[2];
    const float* b1 = (const float*)d_in[3];
    const float* Wg = (const float*)d_in[4];
    const float* bg = (const float*)d_in[5];
    const float* W2 = (const float*)d_in[6];
    const float* b2 = (const float*)d_in[7];
    float* out = (float*)d_out;

    const int NB_N  = (N_NODES + 255) / 256;
    const int NB_E4 = (N_EDGES / 4 + 255) / 256;
    const int NB_G  = (N_NODES * 32 + 255) / 256;

    k_dummy<<<1, 32>>>();                                   // launch 1
    k_prep<<<NB_N, 256>>>(e);                               // launch 2
    k_fill<<<NB_E4, 256>>>(e);                              // launch 3
    k_gemm1<<<GB_GEMM, 256>>>((const float4*)x, W1, b1, Wg); // launch 4 (profiled)
    k_gather_final<<<NB_G, 256>>>(W2, b2, bg, out);         // launch 5
}

// round 11
// speedup vs baseline: 1.2068x; 1.2068x over previous
#include <cuda_runtime.h>
#include <cstdint>

#define N_NODES 100000
#define N_EDGES 3200000
#define F_IN    512
#define HID     16
#define N_CLASSES 40
#define CAP     128   // per-node in-edge bucket capacity

#define WARPS_PB 8
#define N_TILES  6250     // N_NODES / 16 (exact)
#define GB_GEMM  782      // ceil(6250 / 8)

// dynamic smem layout (floats):
//   [0, 8192)            W1 interleaved: float2[k=512][g=8] = (W1T[k][g], W1T[k][g+8])
//   [8192 + w*1088, ...) per-warp x tile: [16 nodes][68] (64 cols + pad4)
//   [16896 + w*320, ...) per-warp h1 tile: [16][20]
#define SMEM_FLOATS 19456
#define SMEM_BYTES  (SMEM_FLOATS * 4)

// Scratch (device globals: allocation-free)
__device__ float g_hs[N_NODES * HID];      // hs = relu(x@W1^T+b1)@Wg^T * rsqrt(deg)
__device__ int   g_cnt[N_NODES];
__device__ int   g_slots[N_NODES * CAP];
__device__ int   g_is64;

__device__ __forceinline__ unsigned totf(float x) {
    unsigned r;
    asm("cvt.rna.tf32.f32 %0, %1;" : "=r"(r) : "f"(x));
    return r;
}
__device__ __forceinline__ void mma_tf32(float* d, const unsigned* a, unsigned b0, unsigned b1) {
    asm volatile(
        "mma.sync.aligned.m16n8k8.row.col.f32.tf32.tf32.f32 "
        "{%0,%1,%2,%3}, {%4,%5,%6,%7}, {%8,%9}, {%0,%1,%2,%3};"
        : "+f"(d[0]), "+f"(d[1]), "+f"(d[2]), "+f"(d[3])
        : "r"(a[0]), "r"(a[1]), "r"(a[2]), "r"(a[3]), "r"(b0), "r"(b1));
}

// ---------- prep: zero counters + dtype detect ----------
__global__ __launch_bounds__(256) void k_prep(const void* e) {
    int i = blockIdx.x * 256 + threadIdx.x;
    if (i < N_NODES) g_cnt[i] = 0;
    if (blockIdx.x == 0 && threadIdx.x < 64) {
        int t = threadIdx.x;
        const long long* p = (const long long*)e;
        long long v = p[(long long)t * (N_EDGES / 64)];   // max 25.2MB: in-bounds
        int ok = (v >= 0 && v < N_NODES) ? 1 : 0;
        unsigned m = __ballot_sync(0xFFFFFFFFu, ok);
        __shared__ unsigned sm2[2];
        if ((t & 31) == 0) sm2[t >> 5] = m;
        __syncthreads();
        if (t == 0) g_is64 = (sm2[0] == 0xFFFFFFFFu && sm2[1] == 0xFFFFFFFFu) ? 1 : 0;
    }
}

// ---------- fill bucketed CSR: 4 edges/thread ----------
__global__ __launch_bounds__(256) void k_fill(const void* __restrict__ e) {
    int t = blockIdx.x * 256 + threadIdx.x;
    if (t >= N_EDGES / 4) return;
    int s[4], d[4];
    if (g_is64) {
        const longlong4* ps = (const longlong4*)e;
        const longlong4* pd = (const longlong4*)((const long long*)e + N_EDGES);
        longlong4 a = ps[t];
        longlong4 b = pd[t];
        s[0] = (int)a.x; s[1] = (int)a.y; s[2] = (int)a.z; s[3] = (int)a.w;
        d[0] = (int)b.x; d[1] = (int)b.y; d[2] = (int)b.z; d[3] = (int)b.w;
    } else {
        const int4* ps = (const int4*)e;
        const int4* pd = (const int4*)((const int*)e + N_EDGES);
        int4 a = ps[t];
        int4 b = pd[t];
        s[0] = a.x; s[1] = a.y; s[2] = a.z; s[3] = a.w;
        d[0] = b.x; d[1] = b.y; d[2] = b.z; d[3] = b.w;
    }
    int pos[4];
    #pragma unroll
    for (int k = 0; k < 4; k++) pos[k] = atomicAdd(&g_cnt[d[k]], 1);
    #pragma unroll
    for (int k = 0; k < 4; k++)
        if (pos[k] < CAP) g_slots[d[k] * CAP + pos[k]] = s[k];
}

// ---------- K0 via tf32 mma.sync: hs = relu(x@W1^T+b1)@Wg^T * rsqrt(deg) ----------
// Warp computes a 16-node tile. W1 read via tiny LDS fragments feeding HMMA;
// Wg fragments register-resident; bias/relu/dinv fused.
__global__ __launch_bounds__(256) void k_gemm1(
    const float4* __restrict__ x4,
    const float* __restrict__ W1,
    const float* __restrict__ b1,
    const float* __restrict__ Wg)
{
    extern __shared__ float sm[];
    float2* w1i = (float2*)sm;

    int tid = threadIdx.x;
    // Stage W1 interleaved tf32: w1i[k*8+g] = (W1[g][k], W1[g+8][k])
    for (int idx = tid; idx < 4096; idx += 256) {
        int k = idx >> 3, g = idx & 7;
        float2 v;
        v.x = __uint_as_float(totf(W1[g * F_IN + k]));
        v.y = __uint_as_float(totf(W1[(g + 8) * F_IN + k]));
        w1i[idx] = v;
    }
    __syncthreads();

    int wid = tid >> 5, lane = tid & 31;
    int gid = lane >> 2, t4 = lane & 3;
    int tile = blockIdx.x * WARPS_PB + wid;
    if (tile >= N_TILES) return;
    int base = tile * 16;

    float* xw = sm + 8192 + wid * 1088;    // [16][68]
    float* hw = sm + 16896 + wid * 320;    // [16][20]

    // Wg fragments (resident): b0/b1 for kstep s (j 8s..), n-half h (j2 8h..)
    unsigned wgb[2][2][2];
    #pragma unroll
    for (int s = 0; s < 2; s++)
        #pragma unroll
        for (int h = 0; h < 2; h++) {
            wgb[s][h][0] = totf(__ldg(&Wg[(gid + 8 * h) * HID + t4 + 8 * s]));
            wgb[s][h][1] = totf(__ldg(&Wg[(gid + 8 * h) * HID + t4 + 4 + 8 * s]));
        }
    // bias values for this lane's columns
    float bb0 = __ldg(&b1[2 * t4]);
    float bb1 = __ldg(&b1[2 * t4 + 1]);
    float bb2 = __ldg(&b1[2 * t4 + 8]);
    float bb3 = __ldg(&b1[2 * t4 + 9]);

    float d0[4] = {0.f, 0.f, 0.f, 0.f};
    float d1[4] = {0.f, 0.f, 0.f, 0.f};

    #pragma unroll 1
    for (int kc = 0; kc < 8; kc++) {
        // stage 16 nodes x 64 k (fp32 -> tf32): coalesced LDG.128
        int nd = 2 * 0 + (lane >> 4);
        int c4 = lane & 15;
        #pragma unroll
        for (int p = 0; p < 8; p++) {
            int node = 2 * p + (lane >> 4);
            float4 v = __ldg(x4 + (long long)(base + node) * (F_IN / 4) + kc * 16 + c4);
            float4 cv;
            cv.x = __uint_as_float(totf(v.x));
            cv.y = __uint_as_float(totf(v.y));
            cv.z = __uint_as_float(totf(v.z));
            cv.w = __uint_as_float(totf(v.w));
            ((float4*)(xw + node * 68))[c4] = cv;
        }
        (void)nd;
        __syncwarp();

        #pragma unroll
        for (int s = 0; s < 8; s++) {
            int kl = s * 8;
            unsigned a[4];
            a[0] = __float_as_uint(xw[gid * 68 + kl + t4]);
            a[1] = __float_as_uint(xw[(gid + 8) * 68 + kl + t4]);
            a[2] = __float_as_uint(xw[gid * 68 + kl + t4 + 4]);
            a[3] = __float_as_uint(xw[(gid + 8) * 68 + kl + t4 + 4]);
            int kg = kc * 64 + kl;
            float2 bA = w1i[(kg + t4) * 8 + gid];
            float2 bB = w1i[(kg + t4 + 4) * 8 + gid];
            mma_tf32(d0, a, __float_as_uint(bA.x), __float_as_uint(bB.x));
            mma_tf32(d1, a, __float_as_uint(bA.y), __float_as_uint(bB.y));
        }
        __syncwarp();
    }

    // bias + relu -> h1 tile [16][20]
    {
        float v;
        v = d0[0] + bb0; hw[gid * 20 + 2 * t4]           = v > 0.f ? v : 0.f;
        v = d0[1] + bb1; hw[gid * 20 + 2 * t4 + 1]       = v > 0.f ? v : 0.f;
        v = d0[2] + bb0; hw[(gid + 8) * 20 + 2 * t4]     = v > 0.f ? v : 0.f;
        v = d0[3] + bb1; hw[(gid + 8) * 20 + 2 * t4 + 1] = v > 0.f ? v : 0.f;
        v = d1[0] + bb2; hw[gid * 20 + 2 * t4 + 8]       = v > 0.f ? v : 0.f;
        v = d1[1] + bb3; hw[gid * 20 + 2 * t4 + 9]       = v > 0.f ? v : 0.f;
        v = d1[2] + bb2; hw[(gid + 8) * 20 + 2 * t4 + 8] = v > 0.f ? v : 0.f;
        v = d1[3] + bb3; hw[(gid + 8) * 20 + 2 * t4 + 9] = v > 0.f ? v : 0.f;
    }
    __syncwarp();

    // hg = h1 @ Wg^T via 2 ksteps x 2 n-halves, Wg frags resident
    float e0[4] = {0.f, 0.f, 0.f, 0.f};
    float e1[4] = {0.f, 0.f, 0.f, 0.f};
    #pragma unroll
    for (int s = 0; s < 2; s++) {
        int kl = s * 8;
        unsigned a[4];
        a[0] = totf(hw[gid * 20 + kl + t4]);
        a[1] = totf(hw[(gid + 8) * 20 + kl + t4]);
        a[2] = totf(hw[gid * 20 + kl + t4 + 4]);
        a[3] = totf(hw[(gid + 8) * 20 + kl + t4 + 4]);
        mma_tf32(e0, a, wgb[s][0][0], wgb[s][0][1]);
        mma_tf32(e1, a, wgb[s][1][0], wgb[s][1][1]);
    }

    // dinv + store to g_hs
    int n0 = base + gid, n1 = n0 + 8;
    float dv0 = rsqrtf((float)(__ldg(&g_cnt[n0]) + 1));
    float dv1 = rsqrtf((float)(__ldg(&g_cnt[n1]) + 1));
    float2 st;
    st.x = e0[0] * dv0; st.y = e0[1] * dv0;
    *(float2*)(g_hs + (long long)n0 * HID + 2 * t4) = st;
    st.x = e1[0] * dv0; st.y = e1[1] * dv0;
    *(float2*)(g_hs + (long long)n0 * HID + 2 * t4 + 8) = st;
    st.x = e0[2] * dv1; st.y = e0[3] * dv1;
    *(float2*)(g_hs + (long long)n1 * HID + 2 * t4) = st;
    st.x = e1[2] * dv1; st.y = e1[3] * dv1;
    *(float2*)(g_hs + (long long)n1 * HID + 2 * t4 + 8) = st;
}

// ---------- fused gather + final ----------
__global__ __launch_bounds__(256) void k_gather_final(
    const float* __restrict__ W2,
    const float* __restrict__ b2,
    const float* __restrict__ bg,
    float* __restrict__ out)
{
    __shared__ float sW2[N_CLASSES * HID];
    __shared__ float sb2[N_CLASSES];
    __shared__ float sbg[HID];
    int tid = threadIdx.x;
    for (int i = tid; i < N_CLASSES * HID; i += 256) sW2[i] = W2[i];
    if (tid < N_CLASSES) sb2[tid] = b2[tid];
    if (tid < HID) sbg[tid] = bg[tid];
    __syncthreads();

    int warp = (blockIdx.x * 256 + tid) >> 5;
    if (warp >= N_NODES) return;
    int lane = tid & 31;
    int g = lane >> 2;
    int f = lane & 3;

    int cnt = __ldg(&g_cnt[warp]);
    int m = cnt < CAP ? cnt : CAP;
    const int* slots = g_slots + warp * CAP;

    int s0 = 0, s1 = 0;
    if (lane < m)      s0 = __ldg(slots + lane);
    if (32 + lane < m) s1 = __ldg(slots + 32 + lane);

    float ax = 0.f, ay = 0.f, az = 0.f, aw = 0.f;
    int lim = m < 64 ? m : 64;
    #pragma unroll 4
    for (int e = 0; e < lim; e += 8) {
        int idx = e + g;
        int sv = (e < 32) ? __shfl_sync(0xFFFFFFFFu, s0, idx)
                          : __shfl_sync(0xFFFFFFFFu, s1, idx - 32);
        if (idx < lim) {
            float4 v = __ldg((const float4*)(g_hs + (long long)sv * HID) + f);
            ax += v.x; ay += v.y; az += v.z; aw += v.w;
        }
    }
    for (int e = 64; e < m; e += 8) {
        int idx = e + g;
        if (idx < m) {
            int sv = __ldg(slots + idx);
            float4 v = __ldg((const float4*)(g_hs + (long long)sv * HID) + f);
            ax += v.x; ay += v.y; az += v.z; aw += v.w;
        }
    }
    #pragma unroll
    for (int off = 4; off < 32; off <<= 1) {
        ax += __shfl_xor_sync(0xFFFFFFFFu, ax, off);
        ay += __shfl_xor_sync(0xFFFFFFFFu, ay, off);
        az += __shfl_xor_sync(0xFFFFFFFFu, az, off);
        aw += __shfl_xor_sync(0xFFFFFFFFu, aw, off);
    }

    float4 self = __ldg((const float4*)(g_hs + (long long)warp * HID) + f);
    float dv = rsqrtf((float)(cnt + 1));
    float hp[4];
    {
        float t0 = (ax + self.x) * dv + sbg[4 * f + 0];
        float t1 = (ay + self.y) * dv + sbg[4 * f + 1];
        float t2 = (az + self.z) * dv + sbg[4 * f + 2];
        float t3 = (aw + self.w) * dv + sbg[4 * f + 3];
        hp[0] = t0 > 0.f ? t0 : 0.f;
        hp[1] = t1 > 0.f ? t1 : 0.f;
        hp[2] = t2 > 0.f ? t2 : 0.f;
        hp[3] = t3 > 0.f ? t3 : 0.f;
    }

    float h[HID];
    #pragma unroll
    for (int a = 0; a < 4; a++) {
        #pragma unroll
        for (int b = 0; b < 4; b++)
            h[a * 4 + b] = __shfl_sync(0xFFFFFFFFu, hp[b], a);
    }

    float l1 = sb2[lane];
    #pragma unroll
    for (int j = 0; j < HID; j++) l1 += h[j] * sW2[lane * HID + j];
    float l2 = -3.4e38f;
    if (lane < N_CLASSES - 32) {
        l2 = sb2[32 + lane];
        #pragma unroll
        for (int j = 0; j < HID; j++) l2 += h[j] * sW2[(32 + lane) * HID + j];
    }

    float mx = fmaxf(l1, l2);
    #pragma unroll
    for (int off = 16; off >= 1; off >>= 1)
        mx = fmaxf(mx, __shfl_xor_sync(0xFFFFFFFFu, mx, off));
    float ee = __expf(l1 - mx) + (lane < N_CLASSES - 32 ? __expf(l2 - mx) : 0.f);
    #pragma unroll
    for (int off = 16; off >= 1; off >>= 1)
        ee += __shfl_xor_sync(0xFFFFFFFFu, ee, off);
    float lse = __logf(ee) + mx;

    float* o = out + (long long)warp * N_CLASSES;
    o[lane] = l1 - lse;
    if (lane < N_CLASSES - 32) o[32 + lane] = l2 - lse;
}

extern "C" void kernel_launch(void* const* d_in, const int* in_sizes, int n_in,
                              void* d_out, int out_size) {
    const float* x  = (const float*)d_in[0];
    const void*  e  = d_in[1];
    const float* W1 = (const float*)d_in[2];
    const float* b1 = (const float*)d_in[3];
    const float* Wg = (const float*)d_in[4];
    const float* bg = (const float*)d_in[5];
    const float* W2 = (const float*)d_in[6];
    const float* b2 = (const float*)d_in[7];
    float* out = (float*)d_out;

    const int NB_N  = (N_NODES + 255) / 256;
    const int NB_E4 = (N_EDGES / 4 + 255) / 256;
    const int NB_G  = (N_NODES * 32 + 255) / 256;

    cudaFuncSetAttribute(k_gemm1, cudaFuncAttributeMaxDynamicSharedMemorySize, SMEM_BYTES);

    k_prep<<<NB_N, 256>>>(e);                                          // launch 1
    k_fill<<<NB_E4, 256>>>(e);                                         // launch 2
    k_gemm1<<<GB_GEMM, 256, SMEM_BYTES>>>((const float4*)x, W1, b1, Wg); // launch 3
    k_gather_final<<<NB_G, 256>>>(W2, b2, bg, out);                    // launch 4 (profiled)
}

// round 12
// speedup vs baseline: 1.4742x; 1.2216x over previous
#include <cuda_runtime.h>
#include <cstdint>

#define N_NODES 100000
#define N_EDGES 3200000
#define F_IN    512
#define HID     16
#define N_CLASSES 40
#define CAP     128   // per-node in-edge bucket capacity

#define WARPS_PB 8
#define N_TILES  6250     // N_NODES / 16 (exact)
#define GB_GEMM  782      // ceil(6250 / 8)

// dynamic smem layout (floats):
//   [0, 8192)            W1 interleaved: float2[k=512][g=8] = (W1T[k][g], W1T[k][g+8])
//   [8192 + w*1088, ...) per-warp x tile [16][68]; h1 tile [16][20] aliased on top
#define SMEM_FLOATS (8192 + WARPS_PB * 1088)   // 16896 floats = 67584 B -> 3 blocks/SM
#define SMEM_BYTES  (SMEM_FLOATS * 4)

// Scratch (device globals: allocation-free)
__device__ float g_hs[N_NODES * HID];      // hs = relu(x@W1^T+b1)@Wg^T * rsqrt(deg)
__device__ int   g_cnt[N_NODES];
__device__ int   g_slots[N_NODES * CAP];
__device__ int   g_is64;

__device__ __forceinline__ unsigned totf(float x) {
    unsigned r;
    asm("cvt.rna.tf32.f32 %0, %1;" : "=r"(r) : "f"(x));
    return r;
}
__device__ __forceinline__ void mma_tf32(float* d, const unsigned* a, unsigned b0, unsigned b1) {
    asm volatile(
        "mma.sync.aligned.m16n8k8.row.col.f32.tf32.tf32.f32 "
        "{%0,%1,%2,%3}, {%4,%5,%6,%7}, {%8,%9}, {%0,%1,%2,%3};"
        : "+f"(d[0]), "+f"(d[1]), "+f"(d[2]), "+f"(d[3])
        : "r"(a[0]), "r"(a[1]), "r"(a[2]), "r"(a[3]), "r"(b0), "r"(b1));
}

// ---------- dummy: shifts launch index so ncu's capture lands on k_gemm1 ----------
__global__ void k_dummy() {}

// ---------- prep: zero counters + dtype detect ----------
__global__ __launch_bounds__(256) void k_prep(const void* e) {
    int i = blockIdx.x * 256 + threadIdx.x;
    if (i < N_NODES) g_cnt[i] = 0;
    if (blockIdx.x == 0 && threadIdx.x < 64) {
        int t = threadIdx.x;
        const long long* p = (const long long*)e;
        long long v = p[(long long)t * (N_EDGES / 64)];   // max 25.2MB: in-bounds
        int ok = (v >= 0 && v < N_NODES) ? 1 : 0;
        unsigned m = __ballot_sync(0xFFFFFFFFu, ok);
        __shared__ unsigned sm2[2];
        if ((t & 31) == 0) sm2[t >> 5] = m;
        __syncthreads();
        if (t == 0) g_is64 = (sm2[0] == 0xFFFFFFFFu && sm2[1] == 0xFFFFFFFFu) ? 1 : 0;
    }
}

// ---------- fill bucketed CSR: 4 edges/thread ----------
__global__ __launch_bounds__(256) void k_fill(const void* __restrict__ e) {
    int t = blockIdx.x * 256 + threadIdx.x;
    if (t >= N_EDGES / 4) return;
    int s[4], d[4];
    if (g_is64) {
        const longlong4* ps = (const longlong4*)e;
        const longlong4* pd = (const longlong4*)((const long long*)e + N_EDGES);
        longlong4 a = ps[t];
        longlong4 b = pd[t];
        s[0] = (int)a.x; s[1] = (int)a.y; s[2] = (int)a.z; s[3] = (int)a.w;
        d[0] = (int)b.x; d[1] = (int)b.y; d[2] = (int)b.z; d[3] = (int)b.w;
    } else {
        const int4* ps = (const int4*)e;
        const int4* pd = (const int4*)((const int*)e + N_EDGES);
        int4 a = ps[t];
        int4 b = pd[t];
        s[0] = a.x; s[1] = a.y; s[2] = a.z; s[3] = a.w;
        d[0] = b.x; d[1] = b.y; d[2] = b.z; d[3] = b.w;
    }
    int pos[4];
    #pragma unroll
    for (int k = 0; k < 4; k++) pos[k] = atomicAdd(&g_cnt[d[k]], 1);
    #pragma unroll
    for (int k = 0; k < 4; k++)
        if (pos[k] < CAP) g_slots[d[k] * CAP + pos[k]] = s[k];
}

// ---------- K0 via tf32 mma.sync, software-pipelined LDG ----------
__global__ __launch_bounds__(256) void k_gemm1(
    const float4* __restrict__ x4,
    const float* __restrict__ W1,
    const float* __restrict__ b1,
    const float* __restrict__ Wg)
{
    extern __shared__ float sm[];
    float2* w1i = (float2*)sm;

    int tid = threadIdx.x;
    // Stage W1 interleaved tf32: w1i[k*8+g] = (W1[g][k], W1[g+8][k])
    for (int idx = tid; idx < 4096; idx += 256) {
        int k = idx >> 3, g = idx & 7;
        float2 v;
        v.x = __uint_as_float(totf(W1[g * F_IN + k]));
        v.y = __uint_as_float(totf(W1[(g + 8) * F_IN + k]));
        w1i[idx] = v;
    }
    __syncthreads();

    int wid = tid >> 5, lane = tid & 31;
    int gid = lane >> 2, t4 = lane & 3;
    int tile = blockIdx.x * WARPS_PB + wid;
    if (tile >= N_TILES) return;
    int base = tile * 16;

    float* xw = sm + 8192 + wid * 1088;    // [16][68]
    float* hw = xw;                        // h1 tile [16][20] aliased after mainloop

    // Wg fragments (register-resident)
    unsigned wgb[2][2][2];
    #pragma unroll
    for (int s = 0; s < 2; s++)
        #pragma unroll
        for (int h = 0; h < 2; h++) {
            wgb[s][h][0] = totf(__ldg(&Wg[(gid + 8 * h) * HID + t4 + 8 * s]));
            wgb[s][h][1] = totf(__ldg(&Wg[(gid + 8 * h) * HID + t4 + 4 + 8 * s]));
        }
    float bb0 = __ldg(&b1[2 * t4]);
    float bb1 = __ldg(&b1[2 * t4 + 1]);
    float bb2 = __ldg(&b1[2 * t4 + 8]);
    float bb3 = __ldg(&b1[2 * t4 + 9]);

    float d0[4] = {0.f, 0.f, 0.f, 0.f};
    float d1[4] = {0.f, 0.f, 0.f, 0.f};

    int c4 = lane & 15;
    int nrow = lane >> 4;    // 0/1

    // preload chunk 0
    float4 pf[8];
    #pragma unroll
    for (int p = 0; p < 8; p++)
        pf[p] = __ldg(x4 + (long long)(base + 2 * p + nrow) * (F_IN / 4) + c4);

    #pragma unroll 1
    for (int kc = 0; kc < 8; kc++) {
        // store current prefetch to smem (tf32-converted)
        #pragma unroll
        for (int p = 0; p < 8; p++) {
            float4 cv;
            cv.x = __uint_as_float(totf(pf[p].x));
            cv.y = __uint_as_float(totf(pf[p].y));
            cv.z = __uint_as_float(totf(pf[p].z));
            cv.w = __uint_as_float(totf(pf[p].w));
            ((float4*)(xw + (2 * p + nrow) * 68))[c4] = cv;
        }
        __syncwarp();
        // issue next chunk's loads BEFORE consuming (latency hidden under MMA work)
        if (kc < 7) {
            #pragma unroll
            for (int p = 0; p < 8; p++)
                pf[p] = __ldg(x4 + (long long)(base + 2 * p + nrow) * (F_IN / 4) + (kc + 1) * 16 + c4);
        }

        #pragma unroll
        for (int s = 0; s < 8; s++) {
            int kl = s * 8;
            unsigned a[4];
            a[0] = __float_as_uint(xw[gid * 68 + kl + t4]);
            a[1] = __float_as_uint(xw[(gid + 8) * 68 + kl + t4]);
            a[2] = __float_as_uint(xw[gid * 68 + kl + t4 + 4]);
            a[3] = __float_as_uint(xw[(gid + 8) * 68 + kl + t4 + 4]);
            int kg = kc * 64 + kl;
            float2 bA = w1i[(kg + t4) * 8 + gid];
            float2 bB = w1i[(kg + t4 + 4) * 8 + gid];
            mma_tf32(d0, a, __float_as_uint(bA.x), __float_as_uint(bB.x));
            mma_tf32(d1, a, __float_as_uint(bA.y), __float_as_uint(bB.y));
        }
        __syncwarp();
    }

    // bias + relu -> h1 tile [16][20] (aliased into xw space)
    {
        float v;
        v = d0[0] + bb0; hw[gid * 20 + 2 * t4]           = v > 0.f ? v : 0.f;
        v = d0[1] + bb1; hw[gid * 20 + 2 * t4 + 1]       = v > 0.f ? v : 0.f;
        v = d0[2] + bb0; hw[(gid + 8) * 20 + 2 * t4]     = v > 0.f ? v : 0.f;
        v = d0[3] + bb1; hw[(gid + 8) * 20 + 2 * t4 + 1] = v > 0.f ? v : 0.f;
        v = d1[0] + bb2; hw[gid * 20 + 2 * t4 + 8]       = v > 0.f ? v : 0.f;
        v = d1[1] + bb3; hw[gid * 20 + 2 * t4 + 9]       = v > 0.f ? v : 0.f;
        v = d1[2] + bb2; hw[(gid + 8) * 20 + 2 * t4 + 8] = v > 0.f ? v : 0.f;
        v = d1[3] + bb3; hw[(gid + 8) * 20 + 2 * t4 + 9] = v > 0.f ? v : 0.f;
    }
    __syncwarp();

    // hg = h1 @ Wg^T (Wg frags resident)
    float e0[4] = {0.f, 0.f, 0.f, 0.f};
    float e1[4] = {0.f, 0.f, 0.f, 0.f};
    #pragma unroll
    for (int s = 0; s < 2; s++) {
        int kl = s * 8;
        unsigned a[4];
        a[0] = totf(hw[gid * 20 + kl + t4]);
        a[1] = totf(hw[(gid + 8) * 20 + kl + t4]);
        a[2] = totf(hw[gid * 20 + kl + t4 + 4]);
        a[3] = totf(hw[(gid + 8) * 20 + kl + t4 + 4]);
        mma_tf32(e0, a, wgb[s][0][0], wgb[s][0][1]);
        mma_tf32(e1, a, wgb[s][1][0], wgb[s][1][1]);
    }

    // dinv + store to g_hs
    int n0 = base + gid, n1 = n0 + 8;
    float dv0 = rsqrtf((float)(__ldg(&g_cnt[n0]) + 1));
    float dv1 = rsqrtf((float)(__ldg(&g_cnt[n1]) + 1));
    float2 st;
    st.x = e0[0] * dv0; st.y = e0[1] * dv0;
    *(float2*)(g_hs + (long long)n0 * HID + 2 * t4) = st;
    st.x = e1[0] * dv0; st.y = e1[1] * dv0;
    *(float2*)(g_hs + (long long)n0 * HID + 2 * t4 + 8) = st;
    st.x = e0[2] * dv1; st.y = e0[3] * dv1;
    *(float2*)(g_hs + (long long)n1 * HID + 2 * t4) = st;
    st.x = e1[2] * dv1; st.y = e1[3] * dv1;
    *(float2*)(g_hs + (long long)n1 * HID + 2 * t4 + 8) = st;
}

// ---------- fused gather + final (sW2 padded stride 17: conflict-free) ----------
__global__ __launch_bounds__(256) void k_gather_final(
    const float* __restrict__ W2,
    const float* __restrict__ b2,
    const float* __restrict__ bg,
    float* __restrict__ out)
{
    __shared__ float sW2[N_CLASSES * 17];
    __shared__ float sb2[N_CLASSES];
    __shared__ float sbg[HID];
    int tid = threadIdx.x;
    for (int i = tid; i < N_CLASSES * HID; i += 256)
        sW2[(i >> 4) * 17 + (i & 15)] = W2[i];
    if (tid < N_CLASSES) sb2[tid] = b2[tid];
    if (tid < HID) sbg[tid] = bg[tid];
    __syncthreads();

    int warp = (blockIdx.x * 256 + tid) >> 5;
    if (warp >= N_NODES) return;
    int lane = tid & 31;
    int g = lane >> 2;
    int f = lane & 3;

    int cnt = __ldg(&g_cnt[warp]);
    int m = cnt < CAP ? cnt : CAP;
    const int* slots = g_slots + warp * CAP;

    int s0 = 0, s1 = 0;
    if (lane < m)      s0 = __ldg(slots + lane);
    if (32 + lane < m) s1 = __ldg(slots + 32 + lane);

    float ax = 0.f, ay = 0.f, az = 0.f, aw = 0.f;
    int lim = m < 64 ? m : 64;
    #pragma unroll 4
    for (int e = 0; e < lim; e += 8) {
        int idx = e + g;
        int sv = (e < 32) ? __shfl_sync(0xFFFFFFFFu, s0, idx)
                          : __shfl_sync(0xFFFFFFFFu, s1, idx - 32);
        if (idx < lim) {
            float4 v = __ldg((const float4*)(g_hs + (long long)sv * HID) + f);
            ax += v.x; ay += v.y; az += v.z; aw += v.w;
        }
    }
    for (int e = 64; e < m; e += 8) {
        int idx = e + g;
        if (idx < m) {
            int sv = __ldg(slots + idx);
            float4 v = __ldg((const float4*)(g_hs + (long long)sv * HID) + f);
            ax += v.x; ay += v.y; az += v.z; aw += v.w;
        }
    }
    #pragma unroll
    for (int off = 4; off < 32; off <<= 1) {
        ax += __shfl_xor_sync(0xFFFFFFFFu, ax, off);
        ay += __shfl_xor_sync(0xFFFFFFFFu, ay, off);
        az += __shfl_xor_sync(0xFFFFFFFFu, az, off);
        aw += __shfl_xor_sync(0xFFFFFFFFu, aw, off);
    }

    float4 self = __ldg((const float4*)(g_hs + (long long)warp * HID) + f);
    float dv = rsqrtf((float)(cnt + 1));
    float hp[4];
    {
        float t0 = (ax + self.x) * dv + sbg[4 * f + 0];
        float t1 = (ay + self.y) * dv + sbg[4 * f + 1];
        float t2 = (az + self.z) * dv + sbg[4 * f + 2];
        float t3 = (aw + self.w) * dv + sbg[4 * f + 3];
        hp[0] = t0 > 0.f ? t0 : 0.f;
        hp[1] = t1 > 0.f ? t1 : 0.f;
        hp[2] = t2 > 0.f ? t2 : 0.f;
        hp[3] = t3 > 0.f ? t3 : 0.f;
    }

    float h[HID];
    #pragma unroll
    for (int a = 0; a < 4; a++) {
        #pragma unroll
        for (int b = 0; b < 4; b++)
            h[a * 4 + b] = __shfl_sync(0xFFFFFFFFu, hp[b], a);
    }

    float l1 = sb2[lane];
    #pragma unroll
    for (int j = 0; j < HID; j++) l1 += h[j] * sW2[lane * 17 + j];
    float l2 = -3.4e38f;
    if (lane < N_CLASSES - 32) {
        l2 = sb2[32 + lane];
        #pragma unroll
        for (int j = 0; j < HID; j++) l2 += h[j] * sW2[(32 + lane) * 17 + j];
    }

    float mx = fmaxf(l1, l2);
    #pragma unroll
    for (int off = 16; off >= 1; off >>= 1)
        mx = fmaxf(mx, __shfl_xor_sync(0xFFFFFFFFu, mx, off));
    float ee = __expf(l1 - mx) + (lane < N_CLASSES - 32 ? __expf(l2 - mx) : 0.f);
    #pragma unroll
    for (int off = 16; off >= 1; off >>= 1)
        ee += __shfl_xor_sync(0xFFFFFFFFu, ee, off);
    float lse = __logf(ee) + mx;

    float* o = out + (long long)warp * N_CLASSES;
    o[lane] = l1 - lse;
    if (lane < N_CLASSES - 32) o[32 + lane] = l2 - lse;
}

extern "C" void kernel_launch(void* const* d_in, const int* in_sizes, int n_in,
                              void* d_out, int out_size) {
    const float* x  = (const float*)d_in[0];
    const void*  e  = d_in[1];
    const float* W1 = (const float*)d_in[2];
    const float* b1 = (const float*)d_in[3];
    const float* Wg = (const float*)d_in[4];
    const float* bg = (const float*)d_in[5];
    const float* W2 = (const float*)d_in[6];
    const float* b2 = (const float*)d_in[7];
    float* out = (float*)d_out;

    const int NB_N  = (N_NODES + 255) / 256;
    const int NB_E4 = (N_EDGES / 4 + 255) / 256;
    const int NB_G  = (N_NODES * 32 + 255) / 256;

    cudaFuncSetAttribute(k_gemm1, cudaFuncAttributeMaxDynamicSharedMemorySize, SMEM_BYTES);

    k_dummy<<<1, 32>>>();                                              // launch 1
    k_prep<<<NB_N, 256>>>(e);                                          // launch 2
    k_fill<<<NB_E4, 256>>>(e);                                         // launch 3
    k_gemm1<<<GB_GEMM, 256, SMEM_BYTES>>>((const float4*)x, W1, b1, Wg); // launch 4 (profiled)
    k_gather_final<<<NB_G, 256>>>(W2, b2, bg, out);                    // launch 5
}